// round 13
// baseline (speedup 1.0000x reference)
#include <cuda_runtime.h>

#define IC 1152
#define OC 10
#define ID 8
#define OD 16
#define OD4 4          // packed f32x2 pairs per od-half
#define BATCH 32
#define NITER 5
#define EPSV 1e-20f
#define ICPB 8
#define NTHREADS 640   // 20 warps: warp=(oc,b-half), lane=odh*16+b%16
#define WSLAB (OC * ID * OD)   // 1280 floats per ic

typedef unsigned long long u64;

__device__ __forceinline__ u64 pk2(float lo, float hi) {
    u64 r; asm("mov.b64 %0, {%1,%2};" : "=l"(r) : "f"(lo), "f"(hi)); return r;
}
__device__ __forceinline__ float2 upk2(u64 v) {
    float2 f; asm("mov.b64 {%0,%1}, %2;" : "=f"(f.x), "=f"(f.y) : "l"(v)); return f;
}
__device__ __forceinline__ u64 mul2(u64 a, u64 b) {
    u64 r; asm("mul.rn.f32x2 %0, %1, %2;" : "=l"(r) : "l"(a), "l"(b)); return r;
}
__device__ __forceinline__ u64 add2(u64 a, u64 b) {
    u64 r; asm("add.rn.f32x2 %0, %1, %2;" : "=l"(r) : "l"(a), "l"(b)); return r;
}
__device__ __forceinline__ u64 fma2(u64 a, u64 b, u64 c) {
    u64 r; asm("fma.rn.f32x2 %0, %1, %2, %3;" : "=l"(r) : "l"(a), "l"(b), "l"(c)); return r;
}
__device__ __forceinline__ unsigned smem_u32(const void* p) {
    return (unsigned)__cvta_generic_to_shared(p);
}
__device__ __forceinline__ void cp_async16(unsigned dst, const void* src) {
    asm volatile("cp.async.ca.shared.global [%0], [%1], 16;" :: "r"(dst), "l"(src));
}

__global__ void zero_out_kernel(float* out, int n) {
    int i = blockIdx.x * blockDim.x + threadIdx.x;
    if (i < n) out[i] = 0.0f;
}

__global__ __launch_bounds__(NTHREADS, 1)
void caps_kernel(const float* __restrict__ x,
                 const float* __restrict__ w,
                 float* __restrict__ out) {
    __shared__ __align__(16) float w_s[2][WSLAB];   // double-buffered ic slab
    __shared__ float x_s[ICPB][BATCH][ID + 1];      // pre-NORMALIZED x, stride 9
    __shared__ float alpha_s[BATCH][OC];

    const int tid  = threadIdx.x;
    const int lane = tid & 31;
    const int warp = tid >> 5;                      // 0..19
    const int oc   = warp >> 1;
    const int b    = ((warp & 1) << 4) | (lane & 15);
    const int odh  = lane >> 4;                     // od half
    const int ic0  = blockIdx.x * ICPB;

    // ---- cp.async slab 0 ----
    if (tid < WSLAB / 4)
        cp_async16(smem_u32((float4*)&w_s[0][0] + tid),
                   (const float4*)(w + (size_t)ic0 * WSLAB) + tid);
    asm volatile("cp.async.commit_group;");

    // ---- load + normalize ALL x for this block's 8 ics (once) ----
    if (tid < ICPB * BATCH) {
        const int kk = tid >> 5, bb = tid & 31;
        const float* xp = x + ((size_t)bb * IC + ic0 + kk) * ID;
        float v[ID]; float sum = 0.0f;
#pragma unroll
        for (int id = 0; id < ID; id++) { v[id] = xp[id]; sum += v[id]; }
        float r = __fdividef(1.0f, sum + EPSV);
#pragma unroll
        for (int id = 0; id < ID; id++) x_s[kk][bb][id] = v[id] * r;
    }
    asm volatile("cp.async.wait_group 0;");
    __syncthreads();

    for (int k = 0; k < ICPB; k++) {
        const int buf = k & 1;

        // ---- prefetch next slab (async, zero registers) ----
        if (k + 1 < ICPB) {
            if (tid < WSLAB / 4)
                cp_async16(smem_u32((float4*)&w_s[buf ^ 1][0] + tid),
                           (const float4*)(w + (size_t)(ic0 + k + 1) * WSLAB) + tid);
            asm volatile("cp.async.commit_group;");
        }

        // ---- weights -> registers, ONCE per ic (16 LDS.128) ----
        const ulonglong2* wv =
            reinterpret_cast<const ulonglong2*>(&w_s[buf][0] + oc * ID * OD) + odh * 2;
        u64 wr[4 * ID];
#pragma unroll
        for (int id = 0; id < ID; id++) {
            ulonglong2 q0 = wv[id * 4];
            ulonglong2 q1 = wv[id * 4 + 1];
            wr[id * 4 + 0] = q0.x;  wr[id * 4 + 1] = q0.y;
            wr[id * 4 + 2] = q1.x;  wr[id * 4 + 3] = q1.y;
        }

        const float* xk = &x_s[k][b][0];    // normalized x row (smem, bcast-safe)

        // ---- NNMF factored, weights in regs ----
        u64 outv2[OD4];
#pragma unroll
        for (int j = 0; j < OD4; j++) outv2[j] = pk2(1.0f / OD, 1.0f / OD);

#pragma unroll
        for (int it = 0; it < NITER; it++) {
            // phase 1: 8 independent half-dots (pure FMA, no loads)
            float s[ID];
#pragma unroll
            for (int id = 0; id < ID; id++) {
                u64 a0 = mul2(outv2[0], wr[id * 4 + 0]);
                u64 a1 = mul2(outv2[1], wr[id * 4 + 1]);
                a0 = fma2(outv2[2], wr[id * 4 + 2], a0);
                a1 = fma2(outv2[3], wr[id * 4 + 3], a1);
                float2 f = upk2(add2(a0, a1));
                s[id] = f.x + f.y;
            }
            // phase 2: partner combine + reciprocal, xn from smem
#pragma unroll
            for (int id = 0; id < ID; id++) {
                float tot = s[id] + __shfl_xor_sync(0xFFFFFFFFu, s[id], 16);
                s[id] = __fdividef(xk[id], tot + EPSV);
            }
            // phase 3: 4 independent half column chains (pure FMA)
            u64 t[OD4];
            {
                u64 sp = pk2(s[0], s[0]);
                t[0] = mul2(sp, wr[0]);
                t[1] = mul2(sp, wr[1]);
                t[2] = mul2(sp, wr[2]);
                t[3] = mul2(sp, wr[3]);
            }
#pragma unroll
            for (int id = 1; id < ID; id++) {
                u64 sp = pk2(s[id], s[id]);
                t[0] = fma2(sp, wr[id * 4 + 0], t[0]);
                t[1] = fma2(sp, wr[id * 4 + 1], t[1]);
                t[2] = fma2(sp, wr[id * 4 + 2], t[2]);
                t[3] = fma2(sp, wr[id * 4 + 3], t[3]);
            }
#pragma unroll
            for (int j = 0; j < OD4; j++)
                outv2[j] = mul2(outv2[j], t[j]);
        }

        // ---- final normalization over OD (cross-partner) ----
        {
            float2 tf = upk2(add2(add2(outv2[0], outv2[1]),
                                  add2(outv2[2], outv2[3])));
            float loc = tf.x + tf.y;
            float tot = loc + __shfl_xor_sync(0xFFFFFFFFu, loc, 16);
            float rn = __fdividef(1.0f, tot + EPSV);
            u64 rn2 = pk2(rn, rn);
#pragma unroll
            for (int j = 0; j < OD4; j++) outv2[j] = mul2(outv2[j], rn2);
        }

        // ---- reconstruct + alpha (weights already in regs) ----
        float ap = 0.0f;
#pragma unroll
        for (int id = 0; id < ID; id++) {
            u64 a0 = mul2(outv2[0], wr[id * 4 + 0]);
            u64 a1 = mul2(outv2[1], wr[id * 4 + 1]);
            a0 = fma2(outv2[2], wr[id * 4 + 2], a0);
            a1 = fma2(outv2[3], wr[id * 4 + 3], a1);
            float2 rf = upk2(add2(a0, a1));
            ap = fmaf(rf.x + rf.y, xk[id], ap);
        }
        float alpha = ap + __shfl_xor_sync(0xFFFFFFFFu, ap, 16);

        if (odh == 0) alpha_s[b][oc] = alpha;
        __syncthreads();   // alpha visible

        float asum = 0.0f;
#pragma unroll
        for (int o2 = 0; o2 < OC; o2++) asum += alpha_s[b][o2];
        float an = alpha * __fdividef(1.0f, asum + EPSV);
        u64 an2 = pk2(an, an);

        // ---- flush this ic's contribution (REDG, no return needed) ----
        float* ob = &out[(b * OC + oc) * OD + odh * 8];
#pragma unroll
        for (int j = 0; j < OD4; j++) {
            float2 f = upk2(mul2(outv2[j], an2));
            atomicAdd(ob + 2 * j,     f.x);
            atomicAdd(ob + 2 * j + 1, f.y);
        }

        // ---- next slab ready + alpha_s safe to rewrite ----
        if (k + 1 < ICPB)
            asm volatile("cp.async.wait_group 0;");
        __syncthreads();
    }
}

extern "C" void kernel_launch(void* const* d_in, const int* in_sizes, int n_in,
                              void* d_out, int out_size) {
    const float* x = (const float*)d_in[0];   // [32, 1152, 8]
    const float* w = (const float*)d_in[1];   // [1152, 10, 8, 16]
    float* out = (float*)d_out;               // [32, 10, 16]

    zero_out_kernel<<<(BATCH * OC * OD + 255) / 256, 256>>>(out, BATCH * OC * OD);
    caps_kernel<<<IC / ICPB, NTHREADS>>>(x, w, out);   // grid = 144 = one wave
}